// round 5
// baseline (speedup 1.0000x reference)
#include <cuda_runtime.h>
#include <cstdint>

// Problem constants: B=32, N=1024, K=16, D=256, L=256
#define ROWS_TOTAL 32768
#define D_DIM 256
#define L_DIM 256
#define KNBR 16

#define TM 64                  // rows per CTA tile
#define KC 16                  // d-chunk size (pipeline granularity)
#define NCHUNK (D_DIM / KC)    // 16
#define SROW 68                // padded row: 68*4B = 272B (float4-aligned, conflict-light)
#define DEPTH 4                // ring depth: producer runs up to 3 chunks ahead

// dynamic smem layout
#define ST_FLOATS (DEPTH * KC * SROW)      // 4352
#define WB_FLOATS (DEPTH * KC * L_DIM)     // 16384
#define SMEM_BYTES ((ST_FLOATS + WB_FLOATS) * 4)   // 82944

// named barriers: 1..4 = "slot b full", 5..8 = "slot b free" (0 reserved)
#define BAR_SYNC(id)   asm volatile("bar.sync %0, 512;"   :: "r"(id))
#define BAR_ARRIVE(id) asm volatile("bar.arrive %0, 512;" :: "r"(id))

__global__ void __launch_bounds__(512, 1) gcn_ws4_kernel(
    const float* __restrict__ targets,
    const float* __restrict__ neighbors,
    const float* __restrict__ avec,
    const float* __restrict__ W,
    float* __restrict__ out)
{
    extern __shared__ float smem[];
    float* sT = smem;                 // [DEPTH][KC][SROW]
    float* wb = smem + ST_FLOATS;     // [DEPTH][KC][L_DIM]

    const int tid  = threadIdx.x;
    const int row0 = blockIdx.x * TM;

    if (tid < 256) {
        // ================= PRODUCER (warps 0..7) =================
        const int r   = tid >> 2;          // 0..63 : row within tile
        const int q   = tid & 3;           // 0..3  : float4 quad within 16-d chunk
        const int row = row0 + r;

        // per-thread degree factor (redundant x4; trivial)
        const float* ap = avec + (size_t)row * (KNBR + 1);
        float f = 0.f;
#pragma unroll
        for (int j = 0; j < KNBR + 1; j++) f += ap[j];
        const float inv = (f > 0.5f) ? (1.0f / f) : 1.0f;

        const float* tgt = targets   + (size_t)row * D_DIM;
        const float* nb  = neighbors + (size_t)row * (KNBR * D_DIM);

        for (int c = 0; c < NCHUNK; c++) {
            const int b = c & (DEPTH - 1);
            if (c >= DEPTH) BAR_SYNC(5 + b);        // wait: slot freed by consumers

            // stage W rows [c*16 .. c*16+16) -> wb[b]  (L2-resident source)
            float* wslot = wb + b * (KC * L_DIM);
#pragma unroll
            for (int v = 0; v < 4; v++) {
                int f4 = v * 256 + tid;             // float4 index into 16x256 chunk
                int wr = f4 >> 6;                   // 64 float4 per row
                int wc = (f4 & 63) << 2;
                *(float4*)&wslot[wr * L_DIM + wc] =
                    *(const float4*)&W[(size_t)(c * KC + wr) * L_DIM + wc];
            }

            // reduce: s[row][d] = (targets + sum_k neighbors) * inv, d in this quad
            const int dbase = c * KC + 4 * q;
            float4 acc = *(const float4*)&tgt[dbase];
#pragma unroll
            for (int k = 0; k < KNBR; k++) {
                float4 v = __ldcs((const float4*)&nb[k * D_DIM + dbase]); // stream, evict-first
                acc.x += v.x; acc.y += v.y; acc.z += v.z; acc.w += v.w;
            }
            acc.x *= inv; acc.y *= inv; acc.z *= inv; acc.w *= inv;

            // transposed store (2-way bank conflict max)
            float* tslot = sT + b * (KC * SROW);
            tslot[(4 * q + 0) * SROW + r] = acc.x;
            tslot[(4 * q + 1) * SROW + r] = acc.y;
            tslot[(4 * q + 2) * SROW + r] = acc.z;
            tslot[(4 * q + 3) * SROW + r] = acc.w;

            __threadfence_block();                  // STS visible before arrive
            BAR_ARRIVE(1 + b);                      // signal: slot full
        }
    } else {
        // ================= CONSUMER (warps 8..15) =================
        const int ct = tid - 256;
        const int ty = ct >> 5;            // 0..7 -> row group of 8
        const int tx = ct & 31;            // cols: pairs at 2*tx + 64*j
        const int r0 = ty * 8;

        unsigned long long acc[8][4];
#pragma unroll
        for (int i = 0; i < 8; i++)
#pragma unroll
            for (int j = 0; j < 4; j++) acc[i][j] = 0ull;

        for (int c = 0; c < NCHUNK; c++) {
            const int b = c & (DEPTH - 1);
            BAR_SYNC(1 + b);                        // wait: slot full

            const float* tslot = sT + b * (KC * SROW);
            const float* wslot = wb + b * (KC * L_DIM);

#pragma unroll
            for (int kk = 0; kk < KC; kk++) {
                // A: 8 rows via two warp-broadcast LDS.128
                const float* srow = &tslot[kk * SROW + r0];
                float4 a0 = *(const float4*)(srow);
                float4 a1 = *(const float4*)(srow + 4);
                float av[8] = {a0.x, a0.y, a0.z, a0.w, a1.x, a1.y, a1.z, a1.w};

                // B: 4 f32x2 pairs, warp-contiguous LDS.64
                unsigned long long bp[4];
#pragma unroll
                for (int j = 0; j < 4; j++)
                    bp[j] = *(const unsigned long long*)&wslot[kk * L_DIM + 2 * tx + 64 * j];

#pragma unroll
                for (int i = 0; i < 8; i++) {
                    unsigned long long ap2;
                    unsigned au = __float_as_uint(av[i]);
                    asm("mov.b64 %0, {%1, %1};" : "=l"(ap2) : "r"(au));
#pragma unroll
                    for (int j = 0; j < 4; j++)
                        asm("fma.rn.f32x2 %0, %1, %2, %0;"
                            : "+l"(acc[i][j]) : "l"(ap2), "l"(bp[j]));
                }
            }

            BAR_ARRIVE(5 + b);                      // signal: slot free
        }

        // epilogue: relu + coalesced float2 stores (256B contiguous per warp)
#pragma unroll
        for (int i = 0; i < 8; i++) {
            const size_t rbase = (size_t)(row0 + r0 + i) * L_DIM;
#pragma unroll
            for (int j = 0; j < 4; j++) {
                unsigned lo_u, hi_u;
                asm("mov.b64 {%0, %1}, %2;" : "=r"(lo_u), "=r"(hi_u) : "l"(acc[i][j]));
                float2 v;
                v.x = fmaxf(__uint_as_float(lo_u), 0.f);
                v.y = fmaxf(__uint_as_float(hi_u), 0.f);
                *(float2*)&out[rbase + 2 * tx + 64 * j] = v;
            }
        }
    }
}

extern "C" void kernel_launch(void* const* d_in, const int* in_sizes, int n_in,
                              void* d_out, int out_size)
{
    const float* targets   = (const float*)d_in[0];
    const float* neighbors = (const float*)d_in[1];
    const float* avec      = (const float*)d_in[2];
    const float* W         = (const float*)d_in[3];
    float* out             = (float*)d_out;

    (void)in_sizes; (void)n_in; (void)out_size;

    cudaFuncSetAttribute(gcn_ws4_kernel,
                         cudaFuncAttributeMaxDynamicSharedMemorySize, SMEM_BYTES);

    const int blocks = ROWS_TOTAL / TM;   // 512
    gcn_ws4_kernel<<<blocks, 512, SMEM_BYTES>>>(targets, neighbors, avec, W, out);
}

// round 8
// speedup vs baseline: 1.0389x; 1.0389x over previous
#include <cuda_runtime.h>
#include <cuda_bf16.h>
#include <cstdint>

// Problem: B=32, N=1024, K=16, D=256, L=256
#define ROWS_TOTAL 32768
#define D_DIM 256
#define L_DIM 256
#define KNBR 16

#define TM 64                  // rows per CTA
#define KC 32                  // d-values per chunk
#define NCHUNK 8
#define THREADS 256

#define PITCH 80               // smem row pitch bytes (32 bf16 data = 64B + 16B pad)
// smem byte offsets
#define A_HI 0
#define A_LO (A_HI + TM * PITCH)          // 5120
#define B_HI (A_LO + TM * PITCH)          // 10240
#define B_LO (B_HI + L_DIM * PITCH)      // 30720
#define SMEM_BYTES (B_LO + L_DIM * PITCH) // 51200

// W^T bf16 hi/lo scratch, [n][k] row-major (512B rows)
__device__ __nv_bfloat16 g_wt_hi[L_DIM * D_DIM];
__device__ __nv_bfloat16 g_wt_lo[L_DIM * D_DIM];

__device__ __forceinline__ uint32_t smem_u32(const void* p) {
    uint32_t a;
    asm("{ .reg .u64 t; cvta.to.shared.u64 t, %1; cvt.u32.u64 %0, t; }" : "=r"(a) : "l"(p));
    return a;
}

__device__ __forceinline__ uint32_t bfpack(float a, float b) {
    unsigned short ua = __bfloat16_as_ushort(__float2bfloat16(a));
    unsigned short ub = __bfloat16_as_ushort(__float2bfloat16(b));
    return (uint32_t)ua | ((uint32_t)ub << 16);
}

__device__ __forceinline__ void ldsm_x4(uint32_t* r, uint32_t addr) {
    asm volatile("ldmatrix.sync.aligned.m8n8.x4.shared.b16 {%0,%1,%2,%3}, [%4];"
                 : "=r"(r[0]), "=r"(r[1]), "=r"(r[2]), "=r"(r[3]) : "r"(addr));
}

__device__ __forceinline__ void ldsm_x2(uint32_t* r, uint32_t addr) {
    asm volatile("ldmatrix.sync.aligned.m8n8.x2.shared.b16 {%0,%1}, [%2];"
                 : "=r"(r[0]), "=r"(r[1]) : "r"(addr));
}

__device__ __forceinline__ void hmma(float* c, const uint32_t* a, const uint32_t* b) {
    asm volatile(
        "mma.sync.aligned.m16n8k16.row.col.f32.bf16.bf16.f32 "
        "{%0,%1,%2,%3}, {%4,%5,%6,%7}, {%8,%9}, {%0,%1,%2,%3};"
        : "+f"(c[0]), "+f"(c[1]), "+f"(c[2]), "+f"(c[3])
        : "r"(a[0]), "r"(a[1]), "r"(a[2]), "r"(a[3]), "r"(b[0]), "r"(b[1]));
}

// ---------------- prep kernel: W[k][n] -> WT_hi/lo[n][k] bf16 ----------------
__global__ void prep_wt(const float* __restrict__ W) {
    int k = blockIdx.x;        // 256
    int n = threadIdx.x;       // 256
    float w = W[(size_t)k * L_DIM + n];
    __nv_bfloat16 hi = __float2bfloat16(w);
    float r = w - __bfloat162float(hi);
    g_wt_hi[(size_t)n * D_DIM + k] = hi;
    g_wt_lo[(size_t)n * D_DIM + k] = __float2bfloat16(r);
}

// ---------------- main fused kernel ----------------
__global__ void __launch_bounds__(THREADS, 2) gcn_hmma_kernel(
    const float* __restrict__ targets,
    const float* __restrict__ neighbors,
    const float* __restrict__ avec,
    float* __restrict__ out)
{
    extern __shared__ char smem[];
    const uint32_t sbase = smem_u32(smem);

    const int tid  = threadIdx.x;
    const int lane = tid & 31;
    const int w    = tid >> 5;
    const int row0 = blockIdx.x * TM;

    // ---- reduction identity: 4 threads per row ----
    const int r = tid >> 2;            // 0..63
    const int q = tid & 3;             // 0..3 (8 d-values each per chunk)
    const int row = row0 + r;

    // degree factor (4x redundant; trivial)
    const float* ap = avec + (size_t)row * (KNBR + 1);
    float fdeg = 0.f;
#pragma unroll
    for (int j = 0; j < KNBR + 1; j++) fdeg += ap[j];
    const float inv = (fdeg > 0.5f) ? (1.0f / fdeg) : 1.0f;

    const float* tgt = targets   + (size_t)row * D_DIM;
    const float* nb  = neighbors + (size_t)row * (KNBR * D_DIM);

    // ---- MMA identity: warp tile 32x64 ----
    const int m0 = (w & 1) * 32;
    const int n0 = (w >> 1) * 64;

    float acc[2][8][4];
#pragma unroll
    for (int i = 0; i < 2; i++)
#pragma unroll
        for (int j = 0; j < 8; j++)
#pragma unroll
            for (int t = 0; t < 4; t++) acc[i][j][t] = 0.f;

    for (int c = 0; c < NCHUNK; c++) {
        __syncthreads();   // previous chunk's ldmatrix reads done

        // ---- stage B chunk: WT hi/lo rows, 64B per row ----
#pragma unroll
        for (int i = 0; i < 8; i++) {
            int p   = i * 256 + tid;          // 0..2047 16B-pieces
            int mat = p >> 10;                // 0: hi, 1: lo
            int n   = (p >> 2) & 255;
            int kq  = p & 3;
            const __nv_bfloat16* src = (mat ? g_wt_lo : g_wt_hi) + (size_t)n * D_DIM + c * KC;
            uint4 v = ((const uint4*)src)[kq];
            *(uint4*)(smem + (mat ? B_LO : B_HI) + n * PITCH + kq * 16) = v;
        }

        // ---- reduce A chunk: 8 d-values per thread, 17 sources ----
        {
            const int db = c * KC + q * 8;
            float4 s0 = *(const float4*)&tgt[db];
            float4 s1 = *(const float4*)&tgt[db + 4];
#pragma unroll
            for (int k = 0; k < KNBR; k++) {
                float4 v0 = __ldcs((const float4*)&nb[k * D_DIM + db]);
                float4 v1 = __ldcs((const float4*)&nb[k * D_DIM + db + 4]);
                s0.x += v0.x; s0.y += v0.y; s0.z += v0.z; s0.w += v0.w;
                s1.x += v1.x; s1.y += v1.y; s1.z += v1.z; s1.w += v1.w;
            }
            s0.x *= inv; s0.y *= inv; s0.z *= inv; s0.w *= inv;
            s1.x *= inv; s1.y *= inv; s1.z *= inv; s1.w *= inv;

            float d[8] = {s0.x, s0.y, s0.z, s0.w, s1.x, s1.y, s1.z, s1.w};
            uint4 hi, lo;
            float h[8];
#pragma unroll
            for (int j = 0; j < 8; j++) h[j] = __bfloat162float(__float2bfloat16(d[j]));
            hi.x = bfpack(d[0], d[1]); hi.y = bfpack(d[2], d[3]);
            hi.z = bfpack(d[4], d[5]); hi.w = bfpack(d[6], d[7]);
            lo.x = bfpack(d[0] - h[0], d[1] - h[1]); lo.y = bfpack(d[2] - h[2], d[3] - h[3]);
            lo.z = bfpack(d[4] - h[4], d[5] - h[5]); lo.w = bfpack(d[6] - h[6], d[7] - h[7]);

            *(uint4*)(smem + A_HI + r * PITCH + q * 16) = hi;
            *(uint4*)(smem + A_LO + r * PITCH + q * 16) = lo;
        }

        __syncthreads();

        // ---- MMA phase: 2 k-steps of 16 ----
#pragma unroll
        for (int ks = 0; ks < 2; ks++) {
            const int kb = ks * 32;           // 16 bf16 = 32B
            // A fragments: hi/lo x 2 m-tiles
            uint32_t Ah[2][4], Al[2][4];
            const uint32_t arow = m0 + (lane & 15);
            const uint32_t acol = kb + ((lane & 16) ? 16 : 0);
#pragma unroll
            for (int mt = 0; mt < 2; mt++) {
                uint32_t off = (arow + mt * 16) * PITCH + acol;
                ldsm_x4(Ah[mt], sbase + A_HI + off);
                ldsm_x4(Al[mt], sbase + A_LO + off);
            }

            const uint32_t brow = n0 + (lane & 7);
            const uint32_t bcol = kb + ((lane & 8) ? 16 : 0);
#pragma unroll
            for (int nt = 0; nt < 8; nt++) {
                uint32_t Bh[2], Bl[2];
                uint32_t off = (brow + nt * 8) * PITCH + bcol;
                ldsm_x2(Bh, sbase + B_HI + off);
                ldsm_x2(Bl, sbase + B_LO + off);
#pragma unroll
                for (int mt = 0; mt < 2; mt++) {
                    hmma(acc[mt][nt], Ah[mt], Bh);
                    hmma(acc[mt][nt], Ah[mt], Bl);
                    hmma(acc[mt][nt], Al[mt], Bh);
                }
            }
        }
    }

    // ---- epilogue: relu + STG (8B per lane, 32B sectors fully used) ----
#pragma unroll
    for (int mt = 0; mt < 2; mt++) {
#pragma unroll
        for (int nt = 0; nt < 8; nt++) {
            const int mrow = row0 + m0 + mt * 16 + (lane >> 2);
            const int col  = n0 + nt * 8 + (lane & 3) * 2;
            float2 v0, v1;
            v0.x = fmaxf(acc[mt][nt][0], 0.f);
            v0.y = fmaxf(acc[mt][nt][1], 0.f);
            v1.x = fmaxf(acc[mt][nt][2], 0.f);
            v1.y = fmaxf(acc[mt][nt][3], 0.f);
            *(float2*)&out[(size_t)mrow * L_DIM + col]       = v0;
            *(float2*)&out[(size_t)(mrow + 8) * L_DIM + col] = v1;
        }
    }
}

extern "C" void kernel_launch(void* const* d_in, const int* in_sizes, int n_in,
                              void* d_out, int out_size)
{
    const float* targets   = (const float*)d_in[0];
    const float* neighbors = (const float*)d_in[1];
    const float* avec      = (const float*)d_in[2];
    const float* W         = (const float*)d_in[3];
    float* out             = (float*)d_out;

    (void)in_sizes; (void)n_in; (void)out_size;

    cudaFuncSetAttribute(gcn_hmma_kernel,
                         cudaFuncAttributeMaxDynamicSharedMemorySize, SMEM_BYTES);

    prep_wt<<<256, 256>>>(W);
    gcn_hmma_kernel<<<ROWS_TOTAL / TM, THREADS, SMEM_BYTES>>>(targets, neighbors, avec, out);
}